// round 5
// baseline (speedup 1.0000x reference)
#include <cuda_runtime.h>
#include <cstdint>

// EGNNRegressor: fully fused per-graph pipeline.
//   grid = 1000 CTAs (one graph each), block = 256 threads.
//   smem: x[200][128], h[200][128], Wtile[32][128], pos (SoA), nbr (u8 local ids).
// Pipeline per CTA:
//   1) load pos, gather emb[z] -> x (smem)
//   2) KNN-5 (exact fp32, matches jax top_k tie-breaking)
//   3) 3x { agg = (x + sum_5 nbr x)/6 ; x = relu(agg @ W + b) }  (fp32 FFMA2 GEMM)
//   4) column mean over 200 rows -> pooled[128]
//   5) MLP 128->64->32->1 (relu, relu, linear) -> out[g]

#define NGRAPH 1000
#define NPG    200
#define KNN    5
#define MD     128

typedef unsigned long long ull;

__device__ __forceinline__ ull dupf(float x) {
    ull r; unsigned u = __float_as_uint(x);
    asm("mov.b64 %0, {%1, %1};" : "=l"(r) : "r"(u));
    return r;
}
__device__ __forceinline__ ull packff(float x, float y) {
    ull r;
    asm("mov.b64 %0, {%1, %2};" : "=l"(r) : "r"(__float_as_uint(x)), "r"(__float_as_uint(y)));
    return r;
}
__device__ __forceinline__ float2 unpf(ull v) {
    unsigned lo, hi;
    asm("mov.b64 {%0, %1}, %2;" : "=r"(lo), "=r"(hi) : "l"(v));
    return make_float2(__uint_as_float(lo), __uint_as_float(hi));
}
// packed fp32x2 FMA: d.xy += a.xy * b.xy  (SASS FFMA2 — 2x fp32 pipe rate)
__device__ __forceinline__ void ffma2(ull& d, ull a, ull b) {
    asm("fma.rn.f32x2 %0, %1, %2, %0;" : "+l"(d) : "l"(a), "l"(b));
}

// smem layout (bytes):
//   xb   : 0        .. 102400   (200*128 f32)
//   hb   : 102400   .. 204800   (200*128 f32)
//   wt   : 204800   .. 221184   (32*128 f32 tile; reused for pooled/MLP scratch)
//   px/py/pz : 221184 .. 223584 (3*200 f32)
//   nbr  : 223584   .. 224584   (200*5 u8 local ids)
#define SMEM_BYTES 224640

__global__ void __launch_bounds__(256, 1)
egnn_fused_kernel(const int* __restrict__ z, const float* __restrict__ pos,
                  const float* __restrict__ emb, const float* __restrict__ convW,
                  const float* __restrict__ convb,
                  const float* __restrict__ rW1, const float* __restrict__ rb1,
                  const float* __restrict__ rW2, const float* __restrict__ rb2,
                  const float* __restrict__ rW3, const float* __restrict__ rb3,
                  float* __restrict__ out)
{
    extern __shared__ float sm[];
    float* xb = sm;                      // 25600 f32
    float* hb = xb + NPG * MD;           // 25600 f32
    float* wt = hb + NPG * MD;           // 4096 f32
    float* px = wt + 4096;
    float* py = px + NPG;
    float* pz = py + NPG;
    unsigned char* nbr = (unsigned char*)(pz + NPG);

    const int g    = blockIdx.x;
    const int tid  = threadIdx.x;
    const int ty   = tid >> 5;           // 0..7
    const int tx   = tid & 31;           // 0..31
    const int base = g * NPG;

    float4*       xb4  = (float4*)xb;
    float4*       hb4  = (float4*)hb;
    const float4* emb4 = (const float4*)emb;

    // ---- load positions (SoA) ----
    for (int i = tid; i < NPG; i += 256) {
        px[i] = pos[(base + i) * 3 + 0];
        py[i] = pos[(base + i) * 3 + 1];
        pz[i] = pos[(base + i) * 3 + 2];
    }
    // ---- gather embedding rows into xb ----
#pragma unroll
    for (int it = 0; it < 25; it++) {
        int i  = it * 8 + ty;
        int zi = z[base + i];                  // broadcast across the warp (L1 hit)
        xb4[i * 32 + tx] = emb4[zi * 32 + tx]; // coalesced 512B per warp, L2 resident
    }
    __syncthreads();

    // ---- KNN-5 (exclude self; strict-< insertion == top_k lower-index tie-break) ----
    if (tid < NPG) {
        const int i = tid;
        const float xi = px[i], yi = py[i], zi = pz[i];
        float bd[5] = {1e30f, 1e30f, 1e30f, 1e30f, 1e30f};
        int   bi[5] = {0, 0, 0, 0, 0};
        for (int j = 0; j < NPG; j++) {
            if (j == i) continue;
            float dx = xi - px[j], dy = yi - py[j], dz = zi - pz[j];
            float d2 = fmaf(dz, dz, fmaf(dy, dy, dx * dx));
            if (d2 < bd[4]) {
                if (d2 < bd[3]) {
                    bd[4] = bd[3]; bi[4] = bi[3];
                    if (d2 < bd[2]) {
                        bd[3] = bd[2]; bi[3] = bi[2];
                        if (d2 < bd[1]) {
                            bd[2] = bd[1]; bi[2] = bi[1];
                            if (d2 < bd[0]) {
                                bd[1] = bd[0]; bi[1] = bi[0];
                                bd[0] = d2; bi[0] = j;
                            } else { bd[1] = d2; bi[1] = j; }
                        } else { bd[2] = d2; bi[2] = j; }
                    } else { bd[3] = d2; bi[3] = j; }
                } else { bd[4] = d2; bi[4] = j; }
            }
        }
#pragma unroll
        for (int k = 0; k < 5; k++) nbr[i * 5 + k] = (unsigned char)bi[k];
    }

    // ---- 3 GCN layers ----
    const float4* Wall4 = (const float4*)convW;
    const ull*    wt2   = (const ull*)wt;
    float4*       wt4   = (float4*)wt;

    for (int l = 0; l < 3; l++) {
        __syncthreads();   // nbr (l==0) / previous-layer xb stores visible

        // aggregation: hb[i] = (xb[i] + sum_k xb[nbr[i][k]]) / 6
#pragma unroll 1
        for (int it = 0; it < 25; it++) {
            int i  = it * 8 + ty;
            int n0 = nbr[i * 5 + 0], n1 = nbr[i * 5 + 1], n2 = nbr[i * 5 + 2];
            int n3 = nbr[i * 5 + 3], n4 = nbr[i * 5 + 4];
            float4 a = xb4[i * 32 + tx];
            float4 v;
            v = xb4[n0 * 32 + tx]; a.x += v.x; a.y += v.y; a.z += v.z; a.w += v.w;
            v = xb4[n1 * 32 + tx]; a.x += v.x; a.y += v.y; a.z += v.z; a.w += v.w;
            v = xb4[n2 * 32 + tx]; a.x += v.x; a.y += v.y; a.z += v.z; a.w += v.w;
            v = xb4[n3 * 32 + tx]; a.x += v.x; a.y += v.y; a.z += v.z; a.w += v.w;
            v = xb4[n4 * 32 + tx]; a.x += v.x; a.y += v.y; a.z += v.z; a.w += v.w;
            const float s = 1.0f / 6.0f;
            a.x *= s; a.y *= s; a.z *= s; a.w *= s;
            hb4[i * 32 + tx] = a;
        }
        __syncthreads();   // hb ready; xb free for overwrite

        // GEMM: xb[i][j] = relu(b[j] + sum_k hb[i][k] * W[k][j])
        // thread tile: 25 rows (i = ty + 8r) x 4 cols (j = 4*tx .. 4*tx+3) as 2 f32x2 accs
        float4 b4 = ((const float4*)(convb + l * MD))[tx];
        ull acc[25][2];
#pragma unroll
        for (int r = 0; r < 25; r++) {
            acc[r][0] = packff(b4.x, b4.y);
            acc[r][1] = packff(b4.z, b4.w);
        }

        for (int t = 0; t < 4; t++) {          // k tiles of 32
            __syncthreads();                   // previous tile fully consumed
#pragma unroll
            for (int q = 0; q < 4; q++) {      // stage W[32t..32t+31][:] -> smem (16KB)
                int lin = q * 256 + tid;
                wt4[lin] = Wall4[l * 4096 + t * 1024 + lin];
            }
            __syncthreads();
#pragma unroll 1
            for (int kc = 0; kc < 8; kc++) {   // k sub-chunks of 4
                ull wp[4][2];
#pragma unroll
                for (int kk = 0; kk < 4; kk++) {
                    int idx = (kc * 4 + kk) * 64 + tx * 2;  // pair (4tx,4tx+1) then (+2,+3)
                    wp[kk][0] = wt2[idx];
                    wp[kk][1] = wt2[idx + 1];
                }
                int hcol = t * 8 + kc;
#pragma unroll
                for (int r = 0; r < 25; r++) {
                    float4 hv = hb4[(ty + 8 * r) * 32 + hcol]; // broadcast across warp
                    ull h0 = dupf(hv.x), h1 = dupf(hv.y), h2 = dupf(hv.z), h3 = dupf(hv.w);
                    ffma2(acc[r][0], h0, wp[0][0]); ffma2(acc[r][1], h0, wp[0][1]);
                    ffma2(acc[r][0], h1, wp[1][0]); ffma2(acc[r][1], h1, wp[1][1]);
                    ffma2(acc[r][0], h2, wp[2][0]); ffma2(acc[r][1], h2, wp[2][1]);
                    ffma2(acc[r][0], h3, wp[3][0]); ffma2(acc[r][1], h3, wp[3][1]);
                }
            }
        }
        // relu + store back to xb
#pragma unroll
        for (int r = 0; r < 25; r++) {
            float2 p0 = unpf(acc[r][0]), p1 = unpf(acc[r][1]);
            float4 o;
            o.x = fmaxf(p0.x, 0.0f); o.y = fmaxf(p0.y, 0.0f);
            o.z = fmaxf(p1.x, 0.0f); o.w = fmaxf(p1.y, 0.0f);
            xb4[(ty + 8 * r) * 32 + tx] = o;
        }
    }
    __syncthreads();

    // ---- mean pooling over 200 rows -> wt[0..127] ----
    if (tid < MD) {
        float s = 0.0f;
        for (int i = 0; i < NPG; i++) s += xb[i * MD + tid];
        wt[tid] = s / 200.0f;
    }
    __syncthreads();

    // ---- regressor MLP ----
    if (tid < 64) {
        float a = rb1[tid];
#pragma unroll 4
        for (int k = 0; k < 128; k++) a = fmaf(wt[k], rW1[k * 64 + tid], a);
        wt[128 + tid] = fmaxf(a, 0.0f);
    }
    __syncthreads();
    if (tid < 32) {
        float a = rb2[tid];
#pragma unroll 4
        for (int k = 0; k < 64; k++) a = fmaf(wt[128 + k], rW2[k * 32 + tid], a);
        wt[192 + tid] = fmaxf(a, 0.0f);
    }
    __syncthreads();
    if (tid == 0) {
        float a = rb3[0];
#pragma unroll
        for (int k = 0; k < 32; k++) a = fmaf(wt[192 + k], rW3[k], a);
        out[g] = a;
    }
}

extern "C" void kernel_launch(void* const* d_in, const int* in_sizes, int n_in,
                              void* d_out, int out_size)
{
    (void)in_sizes; (void)n_in; (void)out_size;
    const int*   z     = (const int*)  d_in[0];
    const float* pos   = (const float*)d_in[1];
    // d_in[2] = batch (unused: batch == node/200 by construction)
    const float* emb   = (const float*)d_in[3];
    const float* convW = (const float*)d_in[4];
    const float* convb = (const float*)d_in[5];
    const float* rW1   = (const float*)d_in[6];
    const float* rb1   = (const float*)d_in[7];
    const float* rW2   = (const float*)d_in[8];
    const float* rb2   = (const float*)d_in[9];
    const float* rW3   = (const float*)d_in[10];
    const float* rb3   = (const float*)d_in[11];
    float*       outp  = (float*)d_out;

    // idempotent, capture-safe (no stream op, no allocation)
    cudaFuncSetAttribute(egnn_fused_kernel,
                         cudaFuncAttributeMaxDynamicSharedMemorySize, SMEM_BYTES);

    egnn_fused_kernel<<<NGRAPH, 256, SMEM_BYTES>>>(
        z, pos, emb, convW, convb, rW1, rb1, rW2, rb2, rW3, rb3, outp);
}